// round 1
// baseline (speedup 1.0000x reference)
#include <cuda_runtime.h>
#include <cuda_bf16.h>
#include <cstdint>

// Problem constants
#define VOCAB  128
#define EDIM   64
#define HDIM   256
#define TLEN   128
#define BATCH  8192
#define NOUT   16384   // VOCAB * TLEN
#define STEPS  15

// ---------------- scratch (static device globals; no allocation) -------------
__device__ __nv_bfloat16 g_P[TLEN * VOCAB * HDIM];       // 8 MB: P[t,v,h]
__device__ float         g_x[BATCH * HDIM];              // 8 MB: input projection
__device__ float         g_Wt[4 * HDIM * HDIM];          // lifW0t, lifW1t, recW0t, recW1t
__device__ float         g_outWt[(size_t)HDIM * NOUT];   // 16 MB: out_W transposed
__device__ unsigned      g_sbits[BATCH * 8];             // final-layer spike bits

// ---------------- small weight transpose: W[j,k] -> Wt[k,j] ------------------
__global__ void k_transpose_small(const float* __restrict__ lif_W,
                                  const float* __restrict__ rec_W) {
    __shared__ float tile[32][33];
    const int m = blockIdx.z;  // 0,1 = lif_W layers; 2,3 = rec_W layers
    const float* src = (m < 2) ? (lif_W + m * HDIM * HDIM)
                               : (rec_W + (m - 2) * HDIM * HDIM);
    int x = blockIdx.x * 32 + threadIdx.x;  // k
    int y = blockIdx.y * 32 + threadIdx.y;  // j
    tile[threadIdx.y][threadIdx.x] = src[y * HDIM + x];
    __syncthreads();
    int xo = blockIdx.y * 32 + threadIdx.x;  // j
    int yo = blockIdx.x * 32 + threadIdx.y;  // k
    g_Wt[m * HDIM * HDIM + yo * HDIM + xo] = tile[threadIdx.x][threadIdx.y];
}

// ---------------- out_W transpose: [NOUT,256] -> [256,NOUT] ------------------
__global__ void k_transpose_outw(const float* __restrict__ out_W) {
    __shared__ float tile[32][33];
    int k = blockIdx.y * 32 + threadIdx.x;
    int n = blockIdx.x * 32 + threadIdx.y;
    tile[threadIdx.y][threadIdx.x] = out_W[(size_t)n * HDIM + k];
    __syncthreads();
    int ko = blockIdx.y * 32 + threadIdx.y;
    int no = blockIdx.x * 32 + threadIdx.x;
    g_outWt[(size_t)ko * NOUT + no] = tile[threadIdx.x][threadIdx.y];
}

// ---------------- P[t,v,h] = dot(emb[v,:], in_W[h, t*64 : t*64+64]) ----------
__global__ void __launch_bounds__(256) k_buildP(const float* __restrict__ emb,
                                                const float* __restrict__ in_W) {
    __shared__ float emb_s[VOCAB * EDIM];  // 32 KB
    const int t = blockIdx.x;
    const int j = threadIdx.x;  // h
    for (int i = j; i < VOCAB * EDIM; i += 256) emb_s[i] = emb[i];
    // thread-private slice of in_W row: 64 contiguous floats
    float4 w4[16];
    const float4* src = (const float4*)(in_W + (size_t)j * 8192 + t * 64);
#pragma unroll
    for (int q = 0; q < 16; q++) w4[q] = src[q];
    __syncthreads();
    for (int v = 0; v < VOCAB; v++) {
        const float* ev = emb_s + v * EDIM;
        float p = 0.f;
#pragma unroll
        for (int q = 0; q < 16; q++) {
            p += ev[4 * q + 0] * w4[q].x;
            p += ev[4 * q + 1] * w4[q].y;
            p += ev[4 * q + 2] * w4[q].z;
            p += ev[4 * q + 3] * w4[q].w;
        }
        g_P[((t << 7) + v) * HDIM + j] = __float2bfloat16(p);
    }
}

// ---------------- x[b,h] = in_b[h] + sum_t P[t, ids[b,t], h] -----------------
__global__ void __launch_bounds__(256) k_gather(const int* __restrict__ ids,
                                                const float* __restrict__ in_b) {
    __shared__ int ids_s[TLEN];
    const int b = blockIdx.x;
    const int j = threadIdx.x;
    if (j < TLEN) ids_s[j] = ids[b * TLEN + j];
    __syncthreads();
    float acc = in_b[j];
#pragma unroll 8
    for (int t = 0; t < TLEN; t++) {
        acc += __bfloat162float(g_P[((t << 7) + ids_s[t]) * HDIM + j]);
    }
    g_x[b * HDIM + j] = acc;
}

// ---------------- fused LIF recurrence (16 batch rows per block) -------------
#define ROWS 16
__global__ void __launch_bounds__(256) k_lif(const float* __restrict__ lif_b) {
    __shared__ float    x_s[ROWS * HDIM];     // 16 KB
    __shared__ unsigned s0b[ROWS][8];
    __shared__ unsigned s1b[ROWS][8];
    __shared__ unsigned u0[8], u1[8];
    __shared__ int any0s, any1s;

    const int j    = threadIdx.x;
    const int lane = j & 31;
    const int wi   = j >> 5;
    const int b0   = blockIdx.x * ROWS;

    for (int i = j; i < ROWS * HDIM; i += 256) x_s[i] = g_x[b0 * HDIM + i];
    if (j < ROWS * 8) { s0b[j >> 3][j & 7] = 0u; s1b[j >> 3][j & 7] = 0u; }
    if (j < 8) { u0[j] = 0u; u1[j] = 0u; }
    if (j == 0) { any0s = 0; any1s = 0; }
    __syncthreads();

    // base0[r] = x[r,:] @ lif_W0[j,:] + lif_b0[j]  (step-invariant)
    float base[ROWS];
#pragma unroll
    for (int r = 0; r < ROWS; r++) base[r] = 0.f;
    const float* W0t = g_Wt;  // [k][j]
#pragma unroll 4
    for (int k = 0; k < HDIM; k++) {
        float wv = W0t[k * HDIM + j];
#pragma unroll
        for (int r = 0; r < ROWS; r++) base[r] += x_s[r * HDIM + k] * wv;
    }
    const float bj0 = lif_b[j];
    const float bj1 = lif_b[HDIM + j];
#pragma unroll
    for (int r = 0; r < ROWS; r++) base[r] += bj0;

    float v0[ROWS], v1[ROWS];
#pragma unroll
    for (int r = 0; r < ROWS; r++) { v0[r] = 0.f; v1[r] = 0.f; }

    for (int step = 0; step < STEPS; step++) {
        // ======== layer 0 ========
        float cur[ROWS];
#pragma unroll
        for (int r = 0; r < ROWS; r++) cur[r] = base[r];
        if (any0s) {  // recurrent term from previous-step layer-0 spikes
            const float* RW0t = g_Wt + 2 * HDIM * HDIM;
            for (int k = 0; k < HDIM; k++) {
                const unsigned bit = 1u << (k & 31);
                const int wk = k >> 5;
                if (u0[wk] & bit) {
                    float wv = RW0t[k * HDIM + j];
#pragma unroll
                    for (int r = 0; r < ROWS; r++)
                        if (s0b[r][wk] & bit) cur[r] += wv;
                }
            }
        }
        unsigned spmask = 0u;
#pragma unroll
        for (int r = 0; r < ROWS; r++) {
            v0[r] = 0.7f * v0[r] + 0.3f * cur[r];
            if (v0[r] >= 1.0f) { spmask |= (1u << r); v0[r] = 0.f; }
        }
        __syncthreads();  // all reads of old s0b complete
#pragma unroll
        for (int r = 0; r < ROWS; r++) {
            unsigned bal = __ballot_sync(0xffffffffu, (spmask >> r) & 1u);
            if (lane == 0) s0b[r][wi] = bal;
        }
        __syncthreads();
        if (j < 8) {
            unsigned o = 0;
#pragma unroll
            for (int r = 0; r < ROWS; r++) o |= s0b[r][j];
            u0[j] = o;
        }
        __syncthreads();
        if (j == 0)
            any0s = (u0[0] | u0[1] | u0[2] | u0[3] | u0[4] | u0[5] | u0[6] | u0[7]) ? 1 : 0;
        __syncthreads();

        // ======== layer 1 (input = NEW layer-0 spikes) ========
#pragma unroll
        for (int r = 0; r < ROWS; r++) cur[r] = bj1;
        if (any0s) {
            const float* LW1t = g_Wt + 1 * HDIM * HDIM;
            for (int k = 0; k < HDIM; k++) {
                const unsigned bit = 1u << (k & 31);
                const int wk = k >> 5;
                if (u0[wk] & bit) {
                    float wv = LW1t[k * HDIM + j];
#pragma unroll
                    for (int r = 0; r < ROWS; r++)
                        if (s0b[r][wk] & bit) cur[r] += wv;
                }
            }
        }
        if (any1s) {
            const float* RW1t = g_Wt + 3 * HDIM * HDIM;
            for (int k = 0; k < HDIM; k++) {
                const unsigned bit = 1u << (k & 31);
                const int wk = k >> 5;
                if (u1[wk] & bit) {
                    float wv = RW1t[k * HDIM + j];
#pragma unroll
                    for (int r = 0; r < ROWS; r++)
                        if (s1b[r][wk] & bit) cur[r] += wv;
                }
            }
        }
        spmask = 0u;
#pragma unroll
        for (int r = 0; r < ROWS; r++) {
            v1[r] = 0.7f * v1[r] + 0.3f * cur[r];
            if (v1[r] >= 1.0f) { spmask |= (1u << r); v1[r] = 0.f; }
        }
        __syncthreads();
#pragma unroll
        for (int r = 0; r < ROWS; r++) {
            unsigned bal = __ballot_sync(0xffffffffu, (spmask >> r) & 1u);
            if (lane == 0) s1b[r][wi] = bal;
        }
        __syncthreads();
        if (j < 8) {
            unsigned o = 0;
#pragma unroll
            for (int r = 0; r < ROWS; r++) o |= s1b[r][j];
            u1[j] = o;
        }
        __syncthreads();
        if (j == 0)
            any1s = (u1[0] | u1[1] | u1[2] | u1[3] | u1[4] | u1[5] | u1[6] | u1[7]) ? 1 : 0;
        __syncthreads();
    }

    if (j < ROWS * 8)
        g_sbits[(b0 + (j >> 3)) * 8 + (j & 7)] = s1b[j >> 3][j & 7];
}

// ---------------- out[b,n] = out_b[n] + sum_{k: s[b,k]} out_Wt[k,n] ----------
__global__ void __launch_bounds__(256) k_out(const float* __restrict__ out_b,
                                             float* __restrict__ out) {
    __shared__ unsigned sb[8];
    const int b = blockIdx.y;
    const int i = threadIdx.x;
    if (i < 8) sb[i] = g_sbits[b * 8 + i];
    __syncthreads();
    unsigned any = sb[0] | sb[1] | sb[2] | sb[3] | sb[4] | sb[5] | sb[6] | sb[7];

    const int nbase = blockIdx.x * 4096;
    float4 acc[4];
#pragma unroll
    for (int u = 0; u < 4; u++)
        acc[u] = *(const float4*)(out_b + nbase + (u * 256 + i) * 4);

    if (any) {
#pragma unroll
        for (int w = 0; w < 8; w++) {
            unsigned m = sb[w];
            while (m) {
                int k = (w << 5) + __ffs(m) - 1;
                m &= m - 1;
                const float* row = g_outWt + (size_t)k * NOUT + nbase;
#pragma unroll
                for (int u = 0; u < 4; u++) {
                    float4 wv = *(const float4*)(row + (u * 256 + i) * 4);
                    acc[u].x += wv.x; acc[u].y += wv.y;
                    acc[u].z += wv.z; acc[u].w += wv.w;
                }
            }
        }
    }

    float* dst = out + (size_t)b * NOUT + nbase;
#pragma unroll
    for (int u = 0; u < 4; u++)
        *(float4*)(dst + (u * 256 + i) * 4) = acc[u];
}

// ---------------- launch ------------------------------------------------------
extern "C" void kernel_launch(void* const* d_in, const int* in_sizes, int n_in,
                              void* d_out, int out_size) {
    const int*   ids   = (const int*)d_in[0];
    const float* emb   = (const float*)d_in[1];
    const float* in_W  = (const float*)d_in[2];
    const float* in_b  = (const float*)d_in[3];
    const float* lif_W = (const float*)d_in[4];
    const float* lif_b = (const float*)d_in[5];
    const float* rec_W = (const float*)d_in[6];
    const float* out_W = (const float*)d_in[7];
    const float* out_b = (const float*)d_in[8];
    float* out = (float*)d_out;

    k_transpose_small<<<dim3(8, 8, 4), dim3(32, 32)>>>(lif_W, rec_W);
    k_transpose_outw<<<dim3(512, 8), dim3(32, 32)>>>(out_W);
    k_buildP<<<TLEN, 256>>>(emb, in_W);
    k_gather<<<BATCH, 256>>>(ids, in_b);
    k_lif<<<BATCH / ROWS, 256>>>(lif_b);
    k_out<<<dim3(4, BATCH), 256>>>(out_b, out);
}

// round 2
// speedup vs baseline: 1.3582x; 1.3582x over previous
#include <cuda_runtime.h>
#include <cuda_bf16.h>
#include <cstdint>

// Problem constants
#define VOCAB  128
#define EDIM   64
#define HDIM   256
#define TLEN   128
#define BATCH  8192
#define NOUT   16384   // VOCAB * TLEN
#define STEPS  15

// ---------------- scratch (static device globals; no allocation) -------------
__device__ __nv_bfloat16 g_P[TLEN * VOCAB * HDIM];       // 8 MB: P[t,v,h]
__device__ float         g_x[BATCH * HDIM];              // 8 MB: input projection
__device__ float         g_Wt[4 * HDIM * HDIM];          // lifW0t, lifW1t, recW0t, recW1t
__device__ float         g_outWt[(size_t)HDIM * NOUT];   // 16 MB: out_W transposed
__device__ unsigned      g_sbits[BATCH * 8];             // final-layer spike bits

// ---------------- small weight transpose: W[j,k] -> Wt[k,j] ------------------
__global__ void k_transpose_small(const float* __restrict__ lif_W,
                                  const float* __restrict__ rec_W) {
    __shared__ float tile[32][33];
    const int m = blockIdx.z;  // 0,1 = lif_W layers; 2,3 = rec_W layers
    const float* src = (m < 2) ? (lif_W + m * HDIM * HDIM)
                               : (rec_W + (m - 2) * HDIM * HDIM);
    int x = blockIdx.x * 32 + threadIdx.x;  // k
    int y = blockIdx.y * 32 + threadIdx.y;  // j
    tile[threadIdx.y][threadIdx.x] = src[y * HDIM + x];
    __syncthreads();
    int xo = blockIdx.y * 32 + threadIdx.x;  // j
    int yo = blockIdx.x * 32 + threadIdx.y;  // k
    g_Wt[m * HDIM * HDIM + yo * HDIM + xo] = tile[threadIdx.x][threadIdx.y];
}

// ---------------- out_W transpose: [NOUT,256] -> [256,NOUT] ------------------
__global__ void k_transpose_outw(const float* __restrict__ out_W) {
    __shared__ float tile[32][33];
    int k = blockIdx.y * 32 + threadIdx.x;
    int n = blockIdx.x * 32 + threadIdx.y;
    tile[threadIdx.y][threadIdx.x] = out_W[(size_t)n * HDIM + k];
    __syncthreads();
    int ko = blockIdx.y * 32 + threadIdx.y;
    int no = blockIdx.x * 32 + threadIdx.x;
    g_outWt[(size_t)ko * NOUT + no] = tile[threadIdx.x][threadIdx.y];
}

// ---------------- P[t,v,h] = dot(emb[v,:], in_W[h, t*64 : t*64+64]) ----------
__global__ void __launch_bounds__(256) k_buildP(const float* __restrict__ emb,
                                                const float* __restrict__ in_W) {
    __shared__ float emb_s[VOCAB * EDIM];  // 32 KB
    const int t = blockIdx.x;
    const int j = threadIdx.x;  // h
    for (int i = j; i < VOCAB * EDIM; i += 256) emb_s[i] = emb[i];
    float4 w4[16];
    const float4* src = (const float4*)(in_W + (size_t)j * 8192 + t * 64);
#pragma unroll
    for (int q = 0; q < 16; q++) w4[q] = src[q];
    __syncthreads();
    for (int v = 0; v < VOCAB; v++) {
        const float* ev = emb_s + v * EDIM;
        float p = 0.f;
#pragma unroll
        for (int q = 0; q < 16; q++) {
            p += ev[4 * q + 0] * w4[q].x;
            p += ev[4 * q + 1] * w4[q].y;
            p += ev[4 * q + 2] * w4[q].z;
            p += ev[4 * q + 3] * w4[q].w;
        }
        g_P[((t << 7) + v) * HDIM + j] = __float2bfloat16(p);
    }
}

// ---------------- x[b,:] = in_b + sum_t P[t, ids[b,t], :] --------------------
// Warp per batch row: each lane owns 8 h-values, loaded as one uint4 (8 bf16).
__device__ __forceinline__ float bf_lo(unsigned u) { return __uint_as_float(u << 16); }
__device__ __forceinline__ float bf_hi(unsigned u) { return __uint_as_float(u & 0xffff0000u); }

__global__ void __launch_bounds__(256) k_gather(const int* __restrict__ ids,
                                                const float* __restrict__ in_b) {
    __shared__ int ids_s[8][TLEN];
    const int lane = threadIdx.x & 31;
    const int w    = threadIdx.x >> 5;
    const int b    = blockIdx.x * 8 + w;

    for (int i = lane; i < TLEN; i += 32) ids_s[w][i] = ids[b * TLEN + i];
    __syncwarp();

    float acc[8];
    {
        const float4 b0 = *(const float4*)(in_b + lane * 8);
        const float4 b1 = *(const float4*)(in_b + lane * 8 + 4);
        acc[0] = b0.x; acc[1] = b0.y; acc[2] = b0.z; acc[3] = b0.w;
        acc[4] = b1.x; acc[5] = b1.y; acc[6] = b1.z; acc[7] = b1.w;
    }

    const uint4* Pb = (const uint4*)g_P;  // 32 uint4 per (t,v) row
#pragma unroll 4
    for (int t = 0; t < TLEN; t++) {
        const int id = ids_s[w][t];
        const uint4 p = Pb[(size_t)((t << 7) + id) * 32 + lane];
        acc[0] += bf_lo(p.x); acc[1] += bf_hi(p.x);
        acc[2] += bf_lo(p.y); acc[3] += bf_hi(p.y);
        acc[4] += bf_lo(p.z); acc[5] += bf_hi(p.z);
        acc[6] += bf_lo(p.w); acc[7] += bf_hi(p.w);
    }

    float* dst = g_x + (size_t)b * HDIM + lane * 8;
    *(float4*)(dst + 0) = make_float4(acc[0], acc[1], acc[2], acc[3]);
    *(float4*)(dst + 4) = make_float4(acc[4], acc[5], acc[6], acc[7]);
}

// ---------------- fused LIF recurrence (16 batch rows per block) -------------
// Fast path: with zero spike input, v_t = base*(1 - 0.7^t) exactly (monotone
// for base > 0), so no layer-0 neuron ever spikes iff base < 1/(1-0.7^15)
// ~= 1.00477 everywhere; layer 1 then sees only its bias. We test against
// 0.9947 (1% conservative slack vs fp rounding of the iterative reference)
// and skip the 15-step loop entirely. Exact iterative loop kept as fallback.
#define ROWS 16
#define SPIKE_LIM 0.9947f

__global__ void __launch_bounds__(256) k_lif(const float* __restrict__ lif_b) {
    __shared__ float    x_s[ROWS * HDIM];     // 16 KB
    __shared__ unsigned s0b[ROWS][8];
    __shared__ unsigned s1b[ROWS][8];
    __shared__ unsigned u0[8], u1[8];
    __shared__ int any0s, any1s;

    const int j    = threadIdx.x;
    const int lane = j & 31;
    const int wi   = j >> 5;
    const int b0   = blockIdx.x * ROWS;

    for (int i = j; i < ROWS * HDIM; i += 256) x_s[i] = g_x[b0 * HDIM + i];
    __syncthreads();

    // base[r] = x[r,:] @ lif_W0[j,:] + lif_b0[j]  (step-invariant)
    float base[ROWS];
#pragma unroll
    for (int r = 0; r < ROWS; r++) base[r] = 0.f;
    const float* W0t = g_Wt;  // [k][j]
    for (int k = 0; k < HDIM; k += 4) {
        const float w0 = W0t[(k + 0) * HDIM + j];
        const float w1 = W0t[(k + 1) * HDIM + j];
        const float w2 = W0t[(k + 2) * HDIM + j];
        const float w3 = W0t[(k + 3) * HDIM + j];
#pragma unroll
        for (int r = 0; r < ROWS; r++) {
            const float4 xv = *(const float4*)&x_s[r * HDIM + k];
            base[r] += xv.x * w0 + xv.y * w1 + xv.z * w2 + xv.w * w3;
        }
    }
    const float bj0 = lif_b[j];
    const float bj1 = lif_b[HDIM + j];
#pragma unroll
    for (int r = 0; r < ROWS; r++) base[r] += bj0;

    // ---- fast path: no spike can ever fire in this block ----
    int ok = (bj1 < SPIKE_LIM);
#pragma unroll
    for (int r = 0; r < ROWS; r++) ok = ok && (base[r] < SPIKE_LIM);
    if (__syncthreads_and(ok)) {
        if (j < ROWS * 8) g_sbits[b0 * 8 + j] = 0u;
        return;
    }

    // ---- exact fallback ----
    if (j < ROWS * 8) { s0b[j >> 3][j & 7] = 0u; s1b[j >> 3][j & 7] = 0u; }
    if (j < 8) { u0[j] = 0u; u1[j] = 0u; }
    if (j == 0) { any0s = 0; any1s = 0; }
    __syncthreads();

    float v0[ROWS], v1[ROWS];
#pragma unroll
    for (int r = 0; r < ROWS; r++) { v0[r] = 0.f; v1[r] = 0.f; }

    for (int step = 0; step < STEPS; step++) {
        // ======== layer 0 ========
        float cur[ROWS];
#pragma unroll
        for (int r = 0; r < ROWS; r++) cur[r] = base[r];
        if (any0s) {
            const float* RW0t = g_Wt + 2 * HDIM * HDIM;
            for (int k = 0; k < HDIM; k++) {
                const unsigned bit = 1u << (k & 31);
                const int wk = k >> 5;
                if (u0[wk] & bit) {
                    float wv = RW0t[k * HDIM + j];
#pragma unroll
                    for (int r = 0; r < ROWS; r++)
                        if (s0b[r][wk] & bit) cur[r] += wv;
                }
            }
        }
        unsigned spmask = 0u;
#pragma unroll
        for (int r = 0; r < ROWS; r++) {
            v0[r] = 0.7f * v0[r] + 0.3f * cur[r];
            if (v0[r] >= 1.0f) { spmask |= (1u << r); v0[r] = 0.f; }
        }
        __syncthreads();
#pragma unroll
        for (int r = 0; r < ROWS; r++) {
            unsigned bal = __ballot_sync(0xffffffffu, (spmask >> r) & 1u);
            if (lane == 0) s0b[r][wi] = bal;
        }
        __syncthreads();
        if (j < 8) {
            unsigned o = 0;
#pragma unroll
            for (int r = 0; r < ROWS; r++) o |= s0b[r][j];
            u0[j] = o;
        }
        __syncthreads();
        if (j == 0)
            any0s = (u0[0] | u0[1] | u0[2] | u0[3] | u0[4] | u0[5] | u0[6] | u0[7]) ? 1 : 0;
        __syncthreads();

        // ======== layer 1 (input = NEW layer-0 spikes) ========
#pragma unroll
        for (int r = 0; r < ROWS; r++) cur[r] = bj1;
        if (any0s) {
            const float* LW1t = g_Wt + 1 * HDIM * HDIM;
            for (int k = 0; k < HDIM; k++) {
                const unsigned bit = 1u << (k & 31);
                const int wk = k >> 5;
                if (u0[wk] & bit) {
                    float wv = LW1t[k * HDIM + j];
#pragma unroll
                    for (int r = 0; r < ROWS; r++)
                        if (s0b[r][wk] & bit) cur[r] += wv;
                }
            }
        }
        if (any1s) {
            const float* RW1t = g_Wt + 3 * HDIM * HDIM;
            for (int k = 0; k < HDIM; k++) {
                const unsigned bit = 1u << (k & 31);
                const int wk = k >> 5;
                if (u1[wk] & bit) {
                    float wv = RW1t[k * HDIM + j];
#pragma unroll
                    for (int r = 0; r < ROWS; r++)
                        if (s1b[r][wk] & bit) cur[r] += wv;
                }
            }
        }
        spmask = 0u;
#pragma unroll
        for (int r = 0; r < ROWS; r++) {
            v1[r] = 0.7f * v1[r] + 0.3f * cur[r];
            if (v1[r] >= 1.0f) { spmask |= (1u << r); v1[r] = 0.f; }
        }
        __syncthreads();
#pragma unroll
        for (int r = 0; r < ROWS; r++) {
            unsigned bal = __ballot_sync(0xffffffffu, (spmask >> r) & 1u);
            if (lane == 0) s1b[r][wi] = bal;
        }
        __syncthreads();
        if (j < 8) {
            unsigned o = 0;
#pragma unroll
            for (int r = 0; r < ROWS; r++) o |= s1b[r][j];
            u1[j] = o;
        }
        __syncthreads();
        if (j == 0)
            any1s = (u1[0] | u1[1] | u1[2] | u1[3] | u1[4] | u1[5] | u1[6] | u1[7]) ? 1 : 0;
        __syncthreads();
    }

    if (j < ROWS * 8)
        g_sbits[(b0 + (j >> 3)) * 8 + (j & 7)] = s1b[j >> 3][j & 7];
}

// ---------------- out[b,n] = out_b[n] + sum_{k: s[b,k]} out_Wt[k,n] ----------
// 8 batch rows per block: out_b is read once per block (8x less LTS traffic),
// and in the common no-spike case the bias vector is written to all 8 rows.
#define OROWS 8
__global__ void __launch_bounds__(256) k_out(const float* __restrict__ out_b,
                                             float* __restrict__ out) {
    __shared__ unsigned sb[OROWS][8];
    const int i  = threadIdx.x;
    const int b0 = blockIdx.y * OROWS;
    if (i < OROWS * 8) sb[i >> 3][i & 7] = g_sbits[(b0 + (i >> 3)) * 8 + (i & 7)];
    __syncthreads();

    unsigned any = 0;
#pragma unroll
    for (int r = 0; r < OROWS; r++)
#pragma unroll
        for (int w = 0; w < 8; w++) any |= sb[r][w];

    const int nbase = blockIdx.x * 4096;
    float4 bias[4];
#pragma unroll
    for (int u = 0; u < 4; u++)
        bias[u] = *(const float4*)(out_b + nbase + (u * 256 + i) * 4);

    if (!any) {
        // common case: identical bias row for all 8 batch rows
#pragma unroll
        for (int r = 0; r < OROWS; r++) {
            float* dst = out + (size_t)(b0 + r) * NOUT + nbase;
#pragma unroll
            for (int u = 0; u < 4; u++)
                __stcs((float4*)(dst + (u * 256 + i) * 4), bias[u]);
        }
        return;
    }

    for (int r = 0; r < OROWS; r++) {
        float4 acc[4];
#pragma unroll
        for (int u = 0; u < 4; u++) acc[u] = bias[u];
#pragma unroll
        for (int w = 0; w < 8; w++) {
            unsigned m = sb[r][w];
            while (m) {
                int k = (w << 5) + __ffs(m) - 1;
                m &= m - 1;
                const float* row = g_outWt + (size_t)k * NOUT + nbase;
#pragma unroll
                for (int u = 0; u < 4; u++) {
                    float4 wv = *(const float4*)(row + (u * 256 + i) * 4);
                    acc[u].x += wv.x; acc[u].y += wv.y;
                    acc[u].z += wv.z; acc[u].w += wv.w;
                }
            }
        }
        float* dst = out + (size_t)(b0 + r) * NOUT + nbase;
#pragma unroll
        for (int u = 0; u < 4; u++)
            __stcs((float4*)(dst + (u * 256 + i) * 4), acc[u]);
    }
}

// ---------------- launch ------------------------------------------------------
extern "C" void kernel_launch(void* const* d_in, const int* in_sizes, int n_in,
                              void* d_out, int out_size) {
    const int*   ids   = (const int*)d_in[0];
    const float* emb   = (const float*)d_in[1];
    const float* in_W  = (const float*)d_in[2];
    const float* in_b  = (const float*)d_in[3];
    const float* lif_W = (const float*)d_in[4];
    const float* lif_b = (const float*)d_in[5];
    const float* rec_W = (const float*)d_in[6];
    const float* out_W = (const float*)d_in[7];
    const float* out_b = (const float*)d_in[8];
    float* out = (float*)d_out;

    k_transpose_small<<<dim3(8, 8, 4), dim3(32, 32)>>>(lif_W, rec_W);
    k_transpose_outw<<<dim3(512, 8), dim3(32, 32)>>>(out_W);
    k_buildP<<<TLEN, 256>>>(emb, in_W);
    k_gather<<<BATCH / 8, 256>>>(ids, in_b);
    k_lif<<<BATCH / ROWS, 256>>>(lif_b);
    k_out<<<dim3(4, BATCH / OROWS), 256>>>(out_b, out);
}

// round 3
// speedup vs baseline: 2.0825x; 1.5332x over previous
#include <cuda_runtime.h>
#include <cuda_bf16.h>
#include <cstdint>

// Problem constants
#define VOCAB  128
#define EDIM   64
#define HDIM   256
#define TLEN   128
#define BATCH  8192
#define NOUT   16384   // VOCAB * TLEN
#define STEPS  15

// true spike limit is 1/(1-0.7^15) ~= 1.00477; use 0.9 for cross-numerics slack
#define LIM_SAFE 0.9f

// ---------------- scratch (static device globals; no allocation) -------------
__device__ __nv_bfloat16 g_P[TLEN * VOCAB * HDIM];       // 8 MB: P[t,v,h]
__device__ float         g_x[BATCH * HDIM];              // 8 MB: input projection
__device__ float         g_Wt[4 * HDIM * HDIM];          // lifW0t, lifW1t, recW0t, recW1t
__device__ unsigned      g_sbits[BATCH * 8];             // final-layer spike bits
__device__ int           g_maxnormsq;                    // max_b ||x[b]||^2 (float bits)
__device__ int           g_flag;                         // 1 = provably no spikes

// ---------------- reset ------------------------------------------------------
__global__ void k_reset() { g_maxnormsq = 0; }

// ---------------- small weight transpose: W[j,k] -> Wt[k,j] (fallback only) --
__global__ void k_transpose_small(const float* __restrict__ lif_W,
                                  const float* __restrict__ rec_W) {
    __shared__ float tile[32][33];
    const int m = blockIdx.z;  // 0,1 = lif_W layers; 2,3 = rec_W layers
    const float* src = (m < 2) ? (lif_W + m * HDIM * HDIM)
                               : (rec_W + (m - 2) * HDIM * HDIM);
    int x = blockIdx.x * 32 + threadIdx.x;  // k
    int y = blockIdx.y * 32 + threadIdx.y;  // j
    tile[threadIdx.y][threadIdx.x] = src[y * HDIM + x];
    __syncthreads();
    int xo = blockIdx.y * 32 + threadIdx.x;  // j
    int yo = blockIdx.x * 32 + threadIdx.y;  // k
    g_Wt[m * HDIM * HDIM + yo * HDIM + xo] = tile[threadIdx.x][threadIdx.y];
}

// ---------------- P[t,v,h] = dot(emb[v,:], in_W[h, t*64 : t*64+64]) ----------
// grid (TLEN, 2): each block handles 64 vocab rows for one t.
__global__ void __launch_bounds__(256) k_buildP(const float* __restrict__ emb,
                                                const float* __restrict__ in_W) {
    __shared__ float emb_s[64 * EDIM];  // 16 KB
    const int t     = blockIdx.x;
    const int vbase = blockIdx.y * 64;
    const int j     = threadIdx.x;  // h
    for (int i = j; i < 64 * EDIM; i += 256) emb_s[i] = emb[vbase * EDIM + i];
    float4 w4[16];
    const float4* src = (const float4*)(in_W + (size_t)j * 8192 + t * 64);
#pragma unroll
    for (int q = 0; q < 16; q++) w4[q] = src[q];
    __syncthreads();
    for (int v = 0; v < 64; v++) {
        const float4* ev4 = (const float4*)(emb_s + v * EDIM);
        float p = 0.f;
#pragma unroll
        for (int q = 0; q < 16; q++) {
            const float4 e = ev4[q];
            p += e.x * w4[q].x + e.y * w4[q].y + e.z * w4[q].z + e.w * w4[q].w;
        }
        g_P[((t << 7) + vbase + v) * HDIM + j] = __float2bfloat16(p);
    }
}

// ---------------- x[b,:] = in_b + sum_t P[t, ids[b,t], :] --------------------
// Warp per batch row, packed bf16x2 accumulation (HADD2). Also computes
// max_b ||x[b]||^2 for the spike-safety certificate.
__global__ void __launch_bounds__(256) k_gather(const int* __restrict__ ids,
                                                const float* __restrict__ in_b) {
    __shared__ int ids_s[8][TLEN];
    __shared__ int blkmax;
    const int lane = threadIdx.x & 31;
    const int w    = threadIdx.x >> 5;
    const int b    = blockIdx.x * 8 + w;

    if (threadIdx.x == 0) blkmax = 0;
    for (int i = lane; i < TLEN; i += 32) ids_s[w][i] = ids[b * TLEN + i];
    __syncthreads();

    __nv_bfloat162 acc0 = __float2bfloat162_rn(0.f);
    __nv_bfloat162 acc1 = acc0, acc2 = acc0, acc3 = acc0;

    const uint4* Pb = (const uint4*)g_P;  // 32 uint4 per (t,v) row
#pragma unroll 4
    for (int t = 0; t < TLEN; t++) {
        const int id = ids_s[w][t];
        const uint4 p = Pb[(size_t)((t << 7) + id) * 32 + lane];
        acc0 = __hadd2(acc0, *(const __nv_bfloat162*)&p.x);
        acc1 = __hadd2(acc1, *(const __nv_bfloat162*)&p.y);
        acc2 = __hadd2(acc2, *(const __nv_bfloat162*)&p.z);
        acc3 = __hadd2(acc3, *(const __nv_bfloat162*)&p.w);
    }

    float v[8];
    {
        float2 f0 = __bfloat1622float2(acc0);
        float2 f1 = __bfloat1622float2(acc1);
        float2 f2 = __bfloat1622float2(acc2);
        float2 f3 = __bfloat1622float2(acc3);
        v[0] = f0.x; v[1] = f0.y; v[2] = f1.x; v[3] = f1.y;
        v[4] = f2.x; v[5] = f2.y; v[6] = f3.x; v[7] = f3.y;
    }
    const float4 b0 = *(const float4*)(in_b + lane * 8);
    const float4 b1 = *(const float4*)(in_b + lane * 8 + 4);
    v[0] += b0.x; v[1] += b0.y; v[2] += b0.z; v[3] += b0.w;
    v[4] += b1.x; v[5] += b1.y; v[6] += b1.z; v[7] += b1.w;

    float* dst = g_x + (size_t)b * HDIM + lane * 8;
    *(float4*)(dst + 0) = make_float4(v[0], v[1], v[2], v[3]);
    *(float4*)(dst + 4) = make_float4(v[4], v[5], v[6], v[7]);

    // row norm^2 -> block max -> global max
    float ns = 0.f;
#pragma unroll
    for (int i = 0; i < 8; i++) ns += v[i] * v[i];
#pragma unroll
    for (int o = 16; o > 0; o >>= 1) ns += __shfl_xor_sync(0xffffffffu, ns, o);
    if (lane == 0) atomicMax(&blkmax, __float_as_int(ns));
    __syncthreads();
    if (threadIdx.x == 0) atomicMax(&g_maxnormsq, blkmax);
}

// ---------------- spike-safety certificate (1 block) -------------------------
// base[b,j] <= ||x[b]|| * ||W0[j]|| + b0[j]  (Cauchy-Schwarz). If this is below
// LIM_SAFE for every j (and layer-1 bias too), no neuron ever spikes.
__global__ void __launch_bounds__(256) k_flag(const float* __restrict__ lif_W,
                                              const float* __restrict__ lif_b) {
    const int j = threadIdx.x;
    float w2 = 0.f;
    const float4* row = (const float4*)(lif_W + (size_t)j * HDIM);
#pragma unroll
    for (int q = 0; q < 64; q++) {
        const float4 wv = row[q];
        w2 += wv.x * wv.x + wv.y * wv.y + wv.z * wv.z + wv.w * wv.w;
    }
    const float maxx = sqrtf(__int_as_float(g_maxnormsq));
    const float bound = maxx * sqrtf(w2) + lif_b[j];
    int ok = (bound < LIM_SAFE) && (lif_b[HDIM + j] < LIM_SAFE);
    ok = __syncthreads_and(ok);
    if (j == 0) g_flag = ok;
}

// ---------------- fused LIF recurrence (16 batch rows per block) -------------
#define ROWS 16
__global__ void __launch_bounds__(256) k_lif(const float* __restrict__ lif_b) {
    if (g_flag) return;  // certificate holds: no spikes anywhere, k_out skips sbits

    __shared__ float    x_s[ROWS * HDIM];     // 16 KB
    __shared__ unsigned s0b[ROWS][8];
    __shared__ unsigned s1b[ROWS][8];
    __shared__ unsigned u0[8], u1[8];
    __shared__ int any0s, any1s;

    const int j    = threadIdx.x;
    const int lane = j & 31;
    const int wi   = j >> 5;
    const int b0   = blockIdx.x * ROWS;

    for (int i = j; i < ROWS * HDIM; i += 256) x_s[i] = g_x[b0 * HDIM + i];
    if (j < ROWS * 8) { s0b[j >> 3][j & 7] = 0u; s1b[j >> 3][j & 7] = 0u; }
    if (j < 8) { u0[j] = 0u; u1[j] = 0u; }
    if (j == 0) { any0s = 0; any1s = 0; }
    __syncthreads();

    // base[r] = x[r,:] @ lif_W0[j,:] + lif_b0[j]  (step-invariant)
    float base[ROWS];
#pragma unroll
    for (int r = 0; r < ROWS; r++) base[r] = 0.f;
    const float* W0t = g_Wt;  // [k][j]
    for (int k = 0; k < HDIM; k += 4) {
        const float w0 = W0t[(k + 0) * HDIM + j];
        const float w1 = W0t[(k + 1) * HDIM + j];
        const float w2 = W0t[(k + 2) * HDIM + j];
        const float w3 = W0t[(k + 3) * HDIM + j];
#pragma unroll
        for (int r = 0; r < ROWS; r++) {
            const float4 xv = *(const float4*)&x_s[r * HDIM + k];
            base[r] += xv.x * w0 + xv.y * w1 + xv.z * w2 + xv.w * w3;
        }
    }
    const float bj0 = lif_b[j];
    const float bj1 = lif_b[HDIM + j];
#pragma unroll
    for (int r = 0; r < ROWS; r++) base[r] += bj0;

    float v0[ROWS], v1[ROWS];
#pragma unroll
    for (int r = 0; r < ROWS; r++) { v0[r] = 0.f; v1[r] = 0.f; }

    for (int step = 0; step < STEPS; step++) {
        // ======== layer 0 ========
        float cur[ROWS];
#pragma unroll
        for (int r = 0; r < ROWS; r++) cur[r] = base[r];
        if (any0s) {
            const float* RW0t = g_Wt + 2 * HDIM * HDIM;
            for (int k = 0; k < HDIM; k++) {
                const unsigned bit = 1u << (k & 31);
                const int wk = k >> 5;
                if (u0[wk] & bit) {
                    float wv = RW0t[k * HDIM + j];
#pragma unroll
                    for (int r = 0; r < ROWS; r++)
                        if (s0b[r][wk] & bit) cur[r] += wv;
                }
            }
        }
        unsigned spmask = 0u;
#pragma unroll
        for (int r = 0; r < ROWS; r++) {
            v0[r] = 0.7f * v0[r] + 0.3f * cur[r];
            if (v0[r] >= 1.0f) { spmask |= (1u << r); v0[r] = 0.f; }
        }
        __syncthreads();
#pragma unroll
        for (int r = 0; r < ROWS; r++) {
            unsigned bal = __ballot_sync(0xffffffffu, (spmask >> r) & 1u);
            if (lane == 0) s0b[r][wi] = bal;
        }
        __syncthreads();
        if (j < 8) {
            unsigned o = 0;
#pragma unroll
            for (int r = 0; r < ROWS; r++) o |= s0b[r][j];
            u0[j] = o;
        }
        __syncthreads();
        if (j == 0)
            any0s = (u0[0] | u0[1] | u0[2] | u0[3] | u0[4] | u0[5] | u0[6] | u0[7]) ? 1 : 0;
        __syncthreads();

        // ======== layer 1 (input = NEW layer-0 spikes) ========
#pragma unroll
        for (int r = 0; r < ROWS; r++) cur[r] = bj1;
        if (any0s) {
            const float* LW1t = g_Wt + 1 * HDIM * HDIM;
            for (int k = 0; k < HDIM; k++) {
                const unsigned bit = 1u << (k & 31);
                const int wk = k >> 5;
                if (u0[wk] & bit) {
                    float wv = LW1t[k * HDIM + j];
#pragma unroll
                    for (int r = 0; r < ROWS; r++)
                        if (s0b[r][wk] & bit) cur[r] += wv;
                }
            }
        }
        if (any1s) {
            const float* RW1t = g_Wt + 3 * HDIM * HDIM;
            for (int k = 0; k < HDIM; k++) {
                const unsigned bit = 1u << (k & 31);
                const int wk = k >> 5;
                if (u1[wk] & bit) {
                    float wv = RW1t[k * HDIM + j];
#pragma unroll
                    for (int r = 0; r < ROWS; r++)
                        if (s1b[r][wk] & bit) cur[r] += wv;
                }
            }
        }
        spmask = 0u;
#pragma unroll
        for (int r = 0; r < ROWS; r++) {
            v1[r] = 0.7f * v1[r] + 0.3f * cur[r];
            if (v1[r] >= 1.0f) { spmask |= (1u << r); v1[r] = 0.f; }
        }
        __syncthreads();
#pragma unroll
        for (int r = 0; r < ROWS; r++) {
            unsigned bal = __ballot_sync(0xffffffffu, (spmask >> r) & 1u);
            if (lane == 0) s1b[r][wi] = bal;
        }
        __syncthreads();
        if (j < 8) {
            unsigned o = 0;
#pragma unroll
            for (int r = 0; r < ROWS; r++) o |= s1b[r][j];
            u1[j] = o;
        }
        __syncthreads();
        if (j == 0)
            any1s = (u1[0] | u1[1] | u1[2] | u1[3] | u1[4] | u1[5] | u1[6] | u1[7]) ? 1 : 0;
        __syncthreads();
    }

    if (j < ROWS * 8)
        g_sbits[(b0 + (j >> 3)) * 8 + (j & 7)] = s1b[j >> 3][j & 7];
}

// ---------------- out[b,n] = out_b[n] + sum_{k: s[b,k]} out_W[n,k] -----------
// 8 batch rows per block. Certificate path: pure bias broadcast (no sbits).
// Spike path (never taken in practice) reads out_W columns directly.
#define OROWS 8
__global__ void __launch_bounds__(256) k_out(const float* __restrict__ out_b,
                                             const float* __restrict__ out_W,
                                             float* __restrict__ out) {
    __shared__ unsigned sb[OROWS][8];
    const int i  = threadIdx.x;
    const int b0 = blockIdx.y * OROWS;
    const int flag = g_flag;

    const int nbase = blockIdx.x * 4096;
    float4 bias[4];
#pragma unroll
    for (int u = 0; u < 4; u++)
        bias[u] = *(const float4*)(out_b + nbase + (u * 256 + i) * 4);

    unsigned any = 0;
    if (!flag) {
        if (i < OROWS * 8) sb[i >> 3][i & 7] = g_sbits[(b0 + (i >> 3)) * 8 + (i & 7)];
        __syncthreads();
#pragma unroll
        for (int r = 0; r < OROWS; r++)
#pragma unroll
            for (int w = 0; w < 8; w++) any |= sb[r][w];
    }

    if (flag || !any) {
        // common case: identical bias row for all 8 batch rows
#pragma unroll
        for (int r = 0; r < OROWS; r++) {
            float* dst = out + (size_t)(b0 + r) * NOUT + nbase;
#pragma unroll
            for (int u = 0; u < 4; u++)
                __stcs((float4*)(dst + (u * 256 + i) * 4), bias[u]);
        }
        return;
    }

    // rare exact path: accumulate out_W columns for set spike bits
    for (int r = 0; r < OROWS; r++) {
        float4 acc[4];
#pragma unroll
        for (int u = 0; u < 4; u++) acc[u] = bias[u];
#pragma unroll
        for (int w = 0; w < 8; w++) {
            unsigned m = sb[r][w];
            while (m) {
                int k = (w << 5) + __ffs(m) - 1;
                m &= m - 1;
#pragma unroll
                for (int u = 0; u < 4; u++) {
                    const int n0 = nbase + (u * 256 + i) * 4;
                    acc[u].x += out_W[(size_t)(n0 + 0) * HDIM + k];
                    acc[u].y += out_W[(size_t)(n0 + 1) * HDIM + k];
                    acc[u].z += out_W[(size_t)(n0 + 2) * HDIM + k];
                    acc[u].w += out_W[(size_t)(n0 + 3) * HDIM + k];
                }
            }
        }
        float* dst = out + (size_t)(b0 + r) * NOUT + nbase;
#pragma unroll
        for (int u = 0; u < 4; u++)
            __stcs((float4*)(dst + (u * 256 + i) * 4), acc[u]);
    }
}

// ---------------- launch ------------------------------------------------------
extern "C" void kernel_launch(void* const* d_in, const int* in_sizes, int n_in,
                              void* d_out, int out_size) {
    const int*   ids   = (const int*)d_in[0];
    const float* emb   = (const float*)d_in[1];
    const float* in_W  = (const float*)d_in[2];
    const float* in_b  = (const float*)d_in[3];
    const float* lif_W = (const float*)d_in[4];
    const float* lif_b = (const float*)d_in[5];
    const float* rec_W = (const float*)d_in[6];
    const float* out_W = (const float*)d_in[7];
    const float* out_b = (const float*)d_in[8];
    float* out = (float*)d_out;

    k_reset<<<1, 1>>>();
    k_transpose_small<<<dim3(8, 8, 4), dim3(32, 32)>>>(lif_W, rec_W);
    k_buildP<<<dim3(TLEN, 2), 256>>>(emb, in_W);
    k_gather<<<BATCH / 8, 256>>>(ids, in_b);
    k_flag<<<1, 256>>>(lif_W, lif_b);
    k_lif<<<BATCH / ROWS, 256>>>(lif_b);
    k_out<<<dim3(4, BATCH / OROWS), 256>>>(out_b, out_W, out);
}